// round 1
// baseline (speedup 1.0000x reference)
#include <cuda_runtime.h>
#include <math.h>

// Problem constants
#define BATCH   32
#define HQ      32
#define DDIM    128
#define KVHN    8
#define GQ      4            // HQ / KVHN
#define TPAGE   64           // tokens per page
#define NPAGES_POOL 2048
#define PPSEQ   64           // pages per sequence
#define NCHUNK  8
#define PAGES_PER_CHUNK 8    // PPSEQ / NCHUNK
#define CHUNK_TOK (PAGES_PER_CHUNK * TPAGE)   // 512

#define KROW_S  132          // padded K row stride in floats (conflict-free)
#define SMEM_FLOATS (4*KROW_S + 256 + 16 + 2*TPAGE*KROW_S)
#define SMEM_BYTES  (SMEM_FLOATS * 4)

// Split-KV scratch (device globals: allocation-guard-safe, zero-initialized)
__device__ float g_pacc[BATCH * KVHN * NCHUNK * GQ * DDIM];   // 4 MB
__device__ float g_pm[BATCH * KVHN * NCHUNK * GQ];
__device__ float g_pl[BATCH * KVHN * NCHUNK * GQ];

__device__ __forceinline__ void cpasync16(float* dst, const float* src) {
    unsigned sa = (unsigned)__cvta_generic_to_shared(dst);
    asm volatile("cp.async.cg.shared.global [%0], [%1], 16;\n" :: "r"(sa), "l"(src));
}
__device__ __forceinline__ void cpcommit() { asm volatile("cp.async.commit_group;\n"); }
__device__ __forceinline__ void cpwait1() { asm volatile("cp.async.wait_group 1;\n"); }
__device__ __forceinline__ void cpwait0() { asm volatile("cp.async.wait_group 0;\n"); }

__global__ __launch_bounds__(256, 2)
void pa_chunk_kernel(const float* __restrict__ q,
                     const float* __restrict__ kp,
                     const float* __restrict__ vp,
                     const int* __restrict__ lengths,
                     const int* __restrict__ pidx)
{
    const int chunk = blockIdx.x;
    const int kv    = blockIdx.y;
    const int b     = blockIdx.z;
    const int tid   = threadIdx.x;

    const int L = lengths[b];
    const int tok_base = chunk * CHUNK_TOK;
    const int pidx_out = ((b * KVHN + kv) * NCHUNK + chunk) * GQ;

    int nvalid = L - tok_base;
    if (nvalid > CHUNK_TOK) nvalid = CHUNK_TOK;
    if (nvalid <= 0) {
        if (tid < GQ) { g_pm[pidx_out + tid] = -1e30f; g_pl[pidx_out + tid] = 0.0f; }
        return;
    }
    const int npages = (nvalid + TPAGE - 1) / TPAGE;
    const int pbase = b * PPSEQ + chunk * PAGES_PER_CHUNK;

    extern __shared__ float smem[];
    float* q_s  = smem;                       // 4 * 132
    float* p_s  = q_s + 4 * KROW_S;           // 64 * 4 (scores then probs), 16B aligned
    float* mred = p_s + 256;                  // [0..3]=m, [4..7]=scale, [8..11]=l
    float* k_s  = mred + 16;                  // double-buffered K tile, 16B aligned

    // Load q for the 4 GQA heads (contiguous in memory)
    {
        const float* qb = q + ((size_t)b * HQ + kv * GQ) * DDIM;
        #pragma unroll
        for (int i = tid; i < GQ * DDIM; i += 256) {
            int g = i >> 7, d = i & 127;
            q_s[g * KROW_S + d] = qb[i];
        }
    }
    if (tid < 4) { mred[tid] = -1e30f; mred[8 + tid] = 0.0f; }

    // score mapping: token = tid>>2, head = tid&3
    const int t_sc = tid >> 2;
    const int h_sc = tid & 3;
    // V mapping: warp = token phase, lane = d/4
    const int t_off = tid >> 5;
    const int d4    = tid & 31;

    float4 acc0 = make_float4(0.f,0.f,0.f,0.f);
    float4 acc1 = make_float4(0.f,0.f,0.f,0.f);
    float4 acc2 = make_float4(0.f,0.f,0.f,0.f);
    float4 acc3 = make_float4(0.f,0.f,0.f,0.f);

    // K prefetch: page i -> buffer i&1
    auto prefetch = [&](int i) {
        int page = pidx[pbase + i];
        const float* src = kp + ((size_t)(kv * NPAGES_POOL + page)) * (TPAGE * DDIM);
        float* dst = k_s + (i & 1) * (TPAGE * KROW_S);
        #pragma unroll
        for (int j = 0; j < 8; j++) {
            int idx = tid + 256 * j;          // 0..2047 float4s
            int row = idx >> 5, c = idx & 31;
            cpasync16(dst + row * KROW_S + c * 4, src + row * DDIM + c * 4);
        }
        cpcommit();
    };

    prefetch(0);

    for (int i = 0; i < npages; i++) {
        const int page_i = pidx[pbase + i];
        if (i + 1 < npages) { prefetch(i + 1); cpwait1(); }
        else                { cpwait0(); }
        __syncthreads();

        // ---- scores for this page ----
        const float4* krow = (const float4*)(k_s + (i & 1) * (TPAGE * KROW_S) + t_sc * KROW_S);
        const float4* qrow = (const float4*)(q_s + h_sc * KROW_S);
        float s = 0.0f;
        #pragma unroll
        for (int j = 0; j < 32; j++) {
            float4 kk = krow[j];
            float4 qq = qrow[j];
            s += kk.x*qq.x + kk.y*qq.y + kk.z*qq.z + kk.w*qq.w;
        }
        const int valid = nvalid - i * TPAGE;      // >= 1
        if (t_sc >= valid) s = -1e30f;
        p_s[t_sc * 4 + h_sc] = s;
        __syncthreads();

        // ---- per-head running max + rescale factor ----
        if (tid < 4) {
            float m = mred[tid];
            float mt = -1e30f;
            #pragma unroll
            for (int t = 0; t < TPAGE; t++) mt = fmaxf(mt, p_s[t * 4 + tid]);
            float mn = fmaxf(m, mt);
            mred[4 + tid] = __expf(m - mn);
            mred[tid] = mn;
        }
        __syncthreads();

        // ---- probabilities ----
        float p = __expf(s - mred[h_sc]);
        p_s[t_sc * 4 + h_sc] = p;
        __syncthreads();

        // ---- l update (threads 0..3) ----
        if (tid < 4) {
            float sum = 0.0f;
            #pragma unroll
            for (int t = 0; t < TPAGE; t++) sum += p_s[t * 4 + tid];
            mred[8 + tid] = mred[8 + tid] * mred[4 + tid] + sum;
        }

        // ---- V accumulate straight from global (coalesced LDG.128) ----
        {
            float s0 = mred[4 + 0], s1 = mred[4 + 1], s2 = mred[4 + 2], s3 = mred[4 + 3];
            acc0.x *= s0; acc0.y *= s0; acc0.z *= s0; acc0.w *= s0;
            acc1.x *= s1; acc1.y *= s1; acc1.z *= s1; acc1.w *= s1;
            acc2.x *= s2; acc2.y *= s2; acc2.z *= s2; acc2.w *= s2;
            acc3.x *= s3; acc3.y *= s3; acc3.z *= s3; acc3.w *= s3;

            const float4* vbase = (const float4*)(vp +
                ((size_t)(kv * NPAGES_POOL + page_i)) * (TPAGE * DDIM));
            const float4* p4s = (const float4*)p_s;
            #pragma unroll
            for (int r = 0; r < 8; r++) {
                int t = t_off + r * 8;
                float4 v4 = vbase[t * 32 + d4];
                float4 pr = p4s[t];               // {p_h0, p_h1, p_h2, p_h3}
                acc0.x += pr.x * v4.x; acc0.y += pr.x * v4.y; acc0.z += pr.x * v4.z; acc0.w += pr.x * v4.w;
                acc1.x += pr.y * v4.x; acc1.y += pr.y * v4.y; acc1.z += pr.y * v4.z; acc1.w += pr.y * v4.w;
                acc2.x += pr.z * v4.x; acc2.y += pr.z * v4.y; acc2.z += pr.z * v4.z; acc2.w += pr.z * v4.w;
                acc3.x += pr.w * v4.x; acc3.y += pr.w * v4.y; acc3.z += pr.w * v4.z; acc3.w += pr.w * v4.w;
            }
        }
        __syncthreads();   // protect p_s / mred before next iteration writes
    }

    // ---- cross-warp reduction of acc (8 token-phases) via smem (reuse k_s) ----
    float4* red4 = (float4*)k_s;
    red4[tid * 4 + 0] = acc0;
    red4[tid * 4 + 1] = acc1;
    red4[tid * 4 + 2] = acc2;
    red4[tid * 4 + 3] = acc3;
    __syncthreads();

    const float* red = k_s;
    #pragma unroll
    for (int rr = 0; rr < 2; rr++) {
        int idx = tid + rr * 256;           // 0..511 -> (g, d)
        int g = idx >> 7, d = idx & 127;
        float sum = 0.0f;
        #pragma unroll
        for (int w = 0; w < 8; w++)
            sum += red[(((w * 32 + (d >> 2)) * 4 + g) << 2) + (d & 3)];
        g_pacc[(size_t)(pidx_out + g) * DDIM + d] = sum;
    }
    if (tid < 4) {
        g_pm[pidx_out + tid] = mred[tid];
        g_pl[pidx_out + tid] = mred[8 + tid];
    }
}

__global__ void pa_combine_kernel(float* __restrict__ out)
{
    const int bh = blockIdx.x;          // 0..1023
    const int b = bh >> 5, h = bh & 31;
    const int kvg = h;                  // kv = h>>2, g = h&3
    const int base = ((b * KVHN + (kvg >> 2)) * NCHUNK) * GQ + (kvg & 3);
    const int d = threadIdx.x;          // 0..127

    float mv[NCHUNK], lv[NCHUNK];
    float M = -1e30f;
    #pragma unroll
    for (int c = 0; c < NCHUNK; c++) {
        mv[c] = g_pm[base + c * GQ];
        lv[c] = g_pl[base + c * GQ];
        if (lv[c] > 0.0f) M = fmaxf(M, mv[c]);
    }
    float num = 0.0f, den = 0.0f;
    #pragma unroll
    for (int c = 0; c < NCHUNK; c++) {
        if (lv[c] > 0.0f) {
            float w = __expf(mv[c] - M);
            num += w * g_pacc[(size_t)(base + c * GQ) * DDIM + d];
            den += w * lv[c];
        }
    }
    out[((size_t)b * HQ + h) * DDIM + d] = num / den;
}

extern "C" void kernel_launch(void* const* d_in, const int* in_sizes, int n_in,
                              void* d_out, int out_size)
{
    const float* q   = (const float*)d_in[0];
    const float* kp  = (const float*)d_in[1];
    const float* vp  = (const float*)d_in[2];
    const int* lens  = (const int*)d_in[3];
    const int* pidx  = (const int*)d_in[4];
    float* out = (float*)d_out;

    cudaFuncSetAttribute(pa_chunk_kernel,
                         cudaFuncAttributeMaxDynamicSharedMemorySize, SMEM_BYTES);

    dim3 grid(NCHUNK, KVHN, BATCH);
    pa_chunk_kernel<<<grid, 256, SMEM_BYTES>>>(q, kp, vp, lens, pidx);
    pa_combine_kernel<<<BATCH * HQ, DDIM>>>(out);
}